// round 3
// baseline (speedup 1.0000x reference)
#include <cuda_runtime.h>
#include <cstddef>

// Problem constants
#define Bb 2
#define Ss 512
#define Hh 8
#define Dd 64
#define Ee 512          // H*D
#define QT 64           // q rows per GEMM block
#define NRU 256         // relative index r in [0,256)
#define RP  258         // sEt pitch in floats ([d][r] transposed, 8B-aligned rows)
#define PPITCH 260      // scatter-kernel Pu pitch (16B-aligned rows for float4)

// Pu scratch: [b][q][h][r] fp32 = 8 MB (fits in L2)
__device__ float g_pu[Bb * Ss * Hh * NRU];

// ---------------- Kernel A: Pu[b,q,h,r] = sum_d Q[b,q,h,d] * E[r, h*64+d] ----------------
// Grid = (8, 8, 2) = 128 blocks -> exactly one wave on 148 SMs.
// 256 threads; thread (w = warp, l = lane): q in {q0+8w .. q0+8w+7}, r-pairs {2(l+32j)}.
__global__ __launch_bounds__(256)
void pu_gemm_kernel(const float* __restrict__ qin,
                    const float* __restrict__ et)
{
    extern __shared__ float sm[];
    float* sEt = sm;                 // [Dd][RP]  E transposed: sEt[d*RP + r]
    float* sQ  = sm + Dd * RP;       // [QT][Dd]

    const int tid = threadIdx.x;
    const int q0  = blockIdx.x * QT;
    const int h   = blockIdx.y;
    const int b   = blockIdx.z;

    // E slice transposed: global coalesced over d; smem store 2-way conflict (one-time).
    for (int i = tid; i < NRU * Dd; i += 256) {
        const int r = i >> 6, d = i & 63;
        sEt[d * RP + r] = et[r * Ee + h * Dd + d];
    }
    // Q tile (coalesced over d)
    for (int i = tid; i < QT * Dd; i += 256) {
        const int qi = i >> 6, d = i & 63;
        sQ[i] = qin[(((size_t)b * Ss + q0 + qi) * Hh + h) * Dd + d];
    }
    __syncthreads();

    const int l = tid & 31;
    const int w = tid >> 5;

    unsigned long long acc[8][4];
    #pragma unroll
    for (int i = 0; i < 8; ++i)
        #pragma unroll
        for (int j = 0; j < 4; ++j) acc[i][j] = 0ULL;

    #pragma unroll 4
    for (int d = 0; d < Dd; ++d) {
        unsigned long long e2[4], q2[8];
        #pragma unroll
        for (int j = 0; j < 4; ++j)   // LDS.64 of (e_r, e_{r+1}), conflict-free
            e2[j] = *(const unsigned long long*)&sEt[d * RP + 2 * (l + 32 * j)];
        #pragma unroll
        for (int i = 0; i < 8; ++i) { // warp-broadcast q, duplicated into both halves
            const unsigned int qb = __float_as_uint(sQ[(8 * w + i) * Dd + d]);
            asm("mov.b64 %0, {%1, %1};" : "=l"(q2[i]) : "r"(qb));
        }
        #pragma unroll
        for (int i = 0; i < 8; ++i)
            #pragma unroll
            for (int j = 0; j < 4; ++j)
                asm("fma.rn.f32x2 %0, %1, %2, %3;"
                    : "=l"(acc[i][j]) : "l"(q2[i]), "l"(e2[j]), "l"(acc[i][j]));
    }

    // Write Pu[b][q][h][r]: lanes write consecutive 8B -> coalesced STG.64.
    #pragma unroll
    for (int i = 0; i < 8; ++i) {
        const size_t base = (((size_t)b * Ss + q0 + 8 * w + i) * Hh + h) * NRU;
        #pragma unroll
        for (int j = 0; j < 4; ++j)
            *(unsigned long long*)&g_pu[base + 2 * (l + 32 * j)] = acc[i][j];
    }
}

// ---------------- Kernel B: out[b,h,q,k] = Pu[b,q,h, mx + x[b,k] - x[b,q]] ----------------
// Block = (q, b). 256 threads. Inline int64/int32 detection + x row load in smem.
__global__ __launch_bounds__(256)
void scatter_kernel(float* __restrict__ out,
                    const int* __restrict__ xw,
                    const int* __restrict__ mxp)
{
    __shared__ float sP[Hh * PPITCH];
    __shared__ int   sX[Ss];
    __shared__ int   sIs64;

    const int tid = threadIdx.x;
    const int q   = blockIdx.x;
    const int b   = blockIdx.y;

    // dtype detection: int64 x -> odd 32-bit words of the first 2 KB are all zero.
    if (tid == 0) sIs64 = 1;
    __syncthreads();
    if (xw[2 * tid + 1] != 0) atomicAnd(&sIs64, 0);

    // Load Pu rows for all 8 heads: 8 KB contiguous, float4.
    const float4* src = (const float4*)&g_pu[(((size_t)b * Ss + q) * Hh) * NRU];
    for (int i = tid; i < Hh * (NRU / 4); i += 256) {
        const int hh = i >> 6, r4 = i & 63;
        *(float4*)&sP[hh * PPITCH + r4 * 4] = src[i];
    }
    __syncthreads();

    // x row for this batch (normalized to int32 in smem)
    const int is64 = sIs64;
    if (is64) {
        sX[tid]       = xw[2 * (b * Ss + tid)];
        sX[tid + 256] = xw[2 * (b * Ss + tid + 256)];
    } else {
        sX[tid]       = xw[b * Ss + tid];
        sX[tid + 256] = xw[b * Ss + tid + 256];
    }
    __syncthreads();

    const int mx = mxp ? mxp[0] : 128;   // LE low word valid for int32/int64
    const int i0 = mx + sX[tid]       - sX[q];
    const int i1 = mx + sX[tid + 256] - sX[q];

    #pragma unroll
    for (int h = 0; h < Hh; ++h) {
        float* orow = out + (((size_t)(b * Hh + h) * Ss + q)) * Ss;
        orow[tid]       = sP[h * PPITCH + i0];
        orow[tid + 256] = sP[h * PPITCH + i1];
    }
}

extern "C" void kernel_launch(void* const* d_in, const int* in_sizes, int n_in,
                              void* d_out, int out_size) {
    const float* q   = (const float*)d_in[0];
    const float* et  = (const float*)d_in[1];
    const int*   xw  = (const int*)d_in[2];
    const int*   mxp = (n_in > 3) ? (const int*)d_in[3] : nullptr;
    float*       out = (float*)d_out;
    (void)in_sizes; (void)out_size;

    const int smemA = (Dd * RP + QT * Dd) * sizeof(float);  // 82,432 B
    cudaFuncSetAttribute(pu_gemm_kernel,
                         cudaFuncAttributeMaxDynamicSharedMemorySize, smemA);

    dim3 gridA(Ss / QT, Hh, Bb);     // 8 x 8 x 2 = 128 blocks (single wave)
    pu_gemm_kernel<<<gridA, 256, smemA>>>(q, et);

    dim3 gridB(Ss, Bb);              // 512 x 2 = 1024 blocks
    scatter_kernel<<<gridB, 256>>>(out, xw, mxp);
}

// round 4
// speedup vs baseline: 1.0154x; 1.0154x over previous
#include <cuda_runtime.h>
#include <cstddef>

// Problem constants
#define Bb 2
#define Ss 512
#define Hh 8
#define Dd 64
#define Ee 512          // H*D
#define QT 64           // q rows per GEMM block
#define NRU 256         // relative index r in [0,256)
#define RH  128         // r values per GEMM block (r-half)
#define EP  66          // sE pitch ([r][d] layout, even & 33-odd -> conflict-free LDS.64)
#define PPITCH 260      // scatter Pu pitch (multiple of 4 for float4 rows)

// Pu scratch: [b][q][h][r] fp32 = 8 MB (fits in L2)
__device__ float g_pu[Bb * Ss * Hh * NRU];

// ---------------- Kernel A: Pu[b,q,h,r0+r] = sum_d Q[b,q,h,d] * E[r0+r, h*64+d] ----------
// Grid = (8 qtiles, 2 r-halves, 16 b*h) = 256 blocks, 256 threads, ~50 KB smem.
// f32x2 lanes = (even d, odd d). Thread (w,l): q rows {8w..8w+7}, r values {l+32j}, j<4.
__global__ __launch_bounds__(256)
void pu_gemm_kernel(const float* __restrict__ qin,
                    const float* __restrict__ et)
{
    extern __shared__ float sm[];
    float* sE = sm;                  // [RH][EP]   E half, row-major [r][d]
    float* sQ = sm + RH * EP;        // [QT][Dd]   row-major [q][d]

    const int tid = threadIdx.x;
    const int q0  = blockIdx.x * QT;
    const int r0  = blockIdx.y * RH;
    const int h   = blockIdx.z & 7;
    const int b   = blockIdx.z >> 3;

    // E half: global coalesced over d, smem conflict-free (d fastest).
    for (int i = tid; i < RH * Dd; i += 256) {
        const int r = i >> 6, d = i & 63;
        sE[r * EP + d] = et[(r0 + r) * Ee + h * Dd + d];
    }
    // Q tile: coalesced over d.
    for (int i = tid; i < QT * Dd; i += 256) {
        const int qi = i >> 6, d = i & 63;
        sQ[i] = qin[(((size_t)b * Ss + q0 + qi) * Hh + h) * Dd + d];
    }
    __syncthreads();

    const int l = tid & 31;
    const int w = tid >> 5;

    unsigned long long acc[8][4];
    #pragma unroll
    for (int i = 0; i < 8; ++i)
        #pragma unroll
        for (int j = 0; j < 4; ++j) acc[i][j] = 0ULL;

    #pragma unroll 4
    for (int d = 0; d < Dd; d += 2) {
        unsigned long long e2[4], q2[8];
        #pragma unroll
        for (int j = 0; j < 4; ++j)   // LDS.64 (E[r][d], E[r][d+1]); lane->r, 33-stride words: conflict-free
            e2[j] = *(const unsigned long long*)&sE[(l + 32 * j) * EP + d];
        #pragma unroll
        for (int i = 0; i < 8; ++i)   // LDS.64 (q[d], q[d+1]); warp-broadcast
            q2[i] = *(const unsigned long long*)&sQ[(8 * w + i) * Dd + d];
        #pragma unroll
        for (int i = 0; i < 8; ++i)
            #pragma unroll
            for (int j = 0; j < 4; ++j)
                asm("fma.rn.f32x2 %0, %1, %2, %3;"
                    : "=l"(acc[i][j]) : "l"(q2[i]), "l"(e2[j]), "l"(acc[i][j]));
    }

    // Reduce (even-d sum + odd-d sum) and store; lanes -> consecutive r: coalesced STG.32.
    #pragma unroll
    for (int i = 0; i < 8; ++i) {
        const size_t base = (((size_t)b * Ss + q0 + 8 * w + i) * Hh + h) * NRU + r0;
        #pragma unroll
        for (int j = 0; j < 4; ++j) {
            float lo, hi;
            asm("mov.b64 {%0, %1}, %2;" : "=f"(lo), "=f"(hi) : "l"(acc[i][j]));
            g_pu[base + l + 32 * j] = lo + hi;
        }
    }
}

// ---------------- Kernel B: out[b,h,q,k] = Pu[b,q,h, mx + x[b,k] - x[b,q]] ----------------
// Block = (q, b), 256 threads. Thread t: heads {4*(t>>7)..+3}, k in [4*(t&127), +4).
__global__ __launch_bounds__(256)
void scatter_kernel(float* __restrict__ out,
                    const int* __restrict__ xw,
                    const int* __restrict__ mxp)
{
    __shared__ float sP[Hh * PPITCH];
    __shared__ int   sX[Ss];
    __shared__ int   sIs64;

    const int tid = threadIdx.x;
    const int q   = blockIdx.x;
    const int b   = blockIdx.y;

    // dtype detection: int64 x -> odd 32-bit words of the first 2 KB are all zero.
    if (tid == 0) sIs64 = 1;
    __syncthreads();
    if (xw[2 * tid + 1] != 0) atomicAnd(&sIs64, 0);

    // Pu rows for all 8 heads: 8 KB contiguous, float4.
    const float4* src = (const float4*)&g_pu[(((size_t)b * Ss + q) * Hh) * NRU];
    for (int i = tid; i < Hh * (NRU / 4); i += 256) {
        const int hh = i >> 6, r4 = i & 63;
        *(float4*)&sP[hh * PPITCH + r4 * 4] = src[i];
    }
    __syncthreads();

    const int is64 = sIs64;
    if (is64) {
        sX[tid]       = xw[2 * (b * Ss + tid)];
        sX[tid + 256] = xw[2 * (b * Ss + tid + 256)];
    } else {
        sX[tid]       = xw[b * Ss + tid];
        sX[tid + 256] = xw[b * Ss + tid + 256];
    }
    __syncthreads();

    const int mx = mxp ? mxp[0] : 128;       // LE low word valid for int32/int64
    const int h0 = (tid >> 7) * 4;           // heads 0-3 or 4-7
    const int k0 = (tid & 127) * 4;
    const int off = mx - sX[q];
    const int i0 = off + sX[k0];
    const int i1 = off + sX[k0 + 1];
    const int i2 = off + sX[k0 + 2];
    const int i3 = off + sX[k0 + 3];

    #pragma unroll
    for (int hh = 0; hh < 4; ++hh) {
        const float* p = &sP[(h0 + hh) * PPITCH];
        float4 v;
        v.x = p[i0]; v.y = p[i1]; v.z = p[i2]; v.w = p[i3];
        float* orow = out + (((size_t)(b * Hh + h0 + hh) * Ss + q)) * Ss;
        *(float4*)&orow[k0] = v;             // lanes -> consecutive 16B: coalesced STG.128
    }
}

extern "C" void kernel_launch(void* const* d_in, const int* in_sizes, int n_in,
                              void* d_out, int out_size) {
    const float* q   = (const float*)d_in[0];
    const float* et  = (const float*)d_in[1];
    const int*   xw  = (const int*)d_in[2];
    const int*   mxp = (n_in > 3) ? (const int*)d_in[3] : nullptr;
    float*       out = (float*)d_out;
    (void)in_sizes; (void)out_size;

    const int smemA = (RH * EP + QT * Dd) * sizeof(float);  // 50,176 B
    cudaFuncSetAttribute(pu_gemm_kernel,
                         cudaFuncAttributeMaxDynamicSharedMemorySize, smemA);

    dim3 gridA(Ss / QT, NRU / RH, Hh * Bb); // 8 x 2 x 16 = 256 blocks
    pu_gemm_kernel<<<gridA, 256, smemA>>>(q, et);

    dim3 gridB(Ss, Bb);                      // 512 x 2 = 1024 blocks
    scatter_kernel<<<gridB, 256>>>(out, xw, mxp);
}

// round 5
// speedup vs baseline: 1.1082x; 1.0915x over previous
#include <cuda_runtime.h>
#include <cstddef>

// Problem constants
#define Bb 2
#define Ss 512
#define Hh 8
#define Dd 64
#define Ee 512          // H*D
#define QT 64           // q rows per GEMM block
#define NRU 256         // relative index r in [0,256)
#define EP  66          // sE pitch ([r][d] layout, conflict-free LDS.64)
#define QG  4           // q rows per scatter block
#define PPITCH 260      // scatter Pu pitch (multiple of 4 for float4 rows)

// Pu scratch: [b][q][h][r] fp32 = 8 MB (fits in L2)
__device__ float g_pu[Bb * Ss * Hh * NRU];

// ---------------- Kernel A: Pu[b,q,h,r] = sum_d Q[b,q,h,d] * E[r, h*64+d] ----------------
// Grid = (8 qtiles, 16 b*h) = 128 blocks (exactly one balanced wave), 512 threads.
// f32x2 lanes = (even d, odd d). Warp w: q rows {4w..4w+3}; lane l: r in {l+32j}, j<8.
__global__ __launch_bounds__(512)
void pu_gemm_kernel(const float* __restrict__ qin,
                    const float* __restrict__ et)
{
    extern __shared__ float sm[];
    float* sE = sm;                  // [NRU][EP]  row-major [r][d]
    float* sQ = sm + NRU * EP;       // [QT][Dd]   row-major [q][d]

    const int tid = threadIdx.x;
    const int q0  = blockIdx.x * QT;
    const int h   = blockIdx.y & 7;
    const int b   = blockIdx.y >> 3;

    // E slice: global coalesced over d, smem conflict-free (d fastest).
    for (int i = tid; i < NRU * Dd; i += 512) {
        const int r = i >> 6, d = i & 63;
        sE[r * EP + d] = et[r * Ee + h * Dd + d];
    }
    // Q tile: coalesced over d.
    for (int i = tid; i < QT * Dd; i += 512) {
        const int qi = i >> 6, d = i & 63;
        sQ[i] = qin[(((size_t)b * Ss + q0 + qi) * Hh + h) * Dd + d];
    }
    __syncthreads();

    const int l = tid & 31;
    const int w = tid >> 5;          // 0..15

    unsigned long long acc[4][8];
    #pragma unroll
    for (int i = 0; i < 4; ++i)
        #pragma unroll
        for (int j = 0; j < 8; ++j) acc[i][j] = 0ULL;

    #pragma unroll 2
    for (int d = 0; d < Dd; d += 2) {
        unsigned long long e2[8], q2[4];
        #pragma unroll
        for (int j = 0; j < 8; ++j)   // LDS.64 (E[r][d], E[r][d+1]); stride-33-word rows: conflict-free
            e2[j] = *(const unsigned long long*)&sE[(l + 32 * j) * EP + d];
        #pragma unroll
        for (int i = 0; i < 4; ++i)   // LDS.64 (q[d], q[d+1]); warp-broadcast
            q2[i] = *(const unsigned long long*)&sQ[(4 * w + i) * Dd + d];
        #pragma unroll
        for (int i = 0; i < 4; ++i)
            #pragma unroll
            for (int j = 0; j < 8; ++j)
                asm("fma.rn.f32x2 %0, %1, %2, %3;"
                    : "=l"(acc[i][j]) : "l"(q2[i]), "l"(e2[j]), "l"(acc[i][j]));
    }

    // Reduce (even-d + odd-d) and store; lanes -> consecutive r: coalesced STG.32.
    #pragma unroll
    for (int i = 0; i < 4; ++i) {
        const size_t base = (((size_t)b * Ss + q0 + 4 * w + i) * Hh + h) * NRU;
        #pragma unroll
        for (int j = 0; j < 8; ++j) {
            float lo, hi;
            asm("mov.b64 {%0, %1}, %2;" : "=f"(lo), "=f"(hi) : "l"(acc[i][j]));
            g_pu[base + l + 32 * j] = lo + hi;
        }
    }
}

// ---------------- Kernel B: out[b,h,q,k] = Pu[b,q,h, mx + x[b,k] - x[b,q]] ----------------
// Block = (4 consecutive q, b). 256 threads. Thread t: heads {4*(t>>7)..+3}, k in [4*(t&127), +4).
__global__ __launch_bounds__(256)
void scatter_kernel(float* __restrict__ out,
                    const int* __restrict__ xw,
                    const int* __restrict__ mxp)
{
    __shared__ float sP[QG][Hh * PPITCH];
    __shared__ int   sX[Ss];
    __shared__ int   sIs64;

    const int tid = threadIdx.x;
    const int q0  = blockIdx.x * QG;
    const int b   = blockIdx.y;

    // dtype detection: int64 x -> odd 32-bit words of the first 2 KB are all zero.
    if (tid == 0) sIs64 = 1;
    __syncthreads();
    if (xw[2 * tid + 1] != 0) atomicAnd(&sIs64, 0);

    // Pu rows for 4 q x 8 heads: 32 KB contiguous, float4 coalesced.
    const float4* src = (const float4*)&g_pu[(((size_t)b * Ss + q0) * Hh) * NRU];
    for (int i = tid; i < QG * Hh * (NRU / 4); i += 256) {
        const int qq = i >> 9;            // /(Hh*64)
        const int hh = (i >> 6) & 7;
        const int r4 = i & 63;
        *(float4*)&sP[qq][hh * PPITCH + r4 * 4] = src[i];
    }
    __syncthreads();

    const int is64 = sIs64;
    if (is64) {
        sX[tid]       = xw[2 * (b * Ss + tid)];
        sX[tid + 256] = xw[2 * (b * Ss + tid + 256)];
    } else {
        sX[tid]       = xw[b * Ss + tid];
        sX[tid + 256] = xw[b * Ss + tid + 256];
    }
    __syncthreads();

    const int mx = mxp ? mxp[0] : 128;       // LE low word valid for int32/int64
    const int h0 = (tid >> 7) * 4;           // heads 0-3 or 4-7
    const int k0 = (tid & 127) * 4;
    const int xk0 = sX[k0], xk1 = sX[k0 + 1], xk2 = sX[k0 + 2], xk3 = sX[k0 + 3];

    #pragma unroll
    for (int qq = 0; qq < QG; ++qq) {
        const int off = mx - sX[q0 + qq];
        const int i0 = off + xk0, i1 = off + xk1, i2 = off + xk2, i3 = off + xk3;
        #pragma unroll
        for (int hh = 0; hh < 4; ++hh) {
            const float* p = &sP[qq][(h0 + hh) * PPITCH];
            float4 v;
            v.x = p[i0]; v.y = p[i1]; v.z = p[i2]; v.w = p[i3];
            float* orow = out + (((size_t)(b * Hh + h0 + hh) * Ss + q0 + qq)) * Ss;
            *(float4*)&orow[k0] = v;         // coalesced STG.128
        }
    }
}

extern "C" void kernel_launch(void* const* d_in, const int* in_sizes, int n_in,
                              void* d_out, int out_size) {
    const float* q   = (const float*)d_in[0];
    const float* et  = (const float*)d_in[1];
    const int*   xw  = (const int*)d_in[2];
    const int*   mxp = (n_in > 3) ? (const int*)d_in[3] : nullptr;
    float*       out = (float*)d_out;
    (void)in_sizes; (void)out_size;

    const int smemA = (NRU * EP + QT * Dd) * sizeof(float);  // 83,968 B
    cudaFuncSetAttribute(pu_gemm_kernel,
                         cudaFuncAttributeMaxDynamicSharedMemorySize, smemA);

    dim3 gridA(Ss / QT, Hh * Bb);            // 8 x 16 = 128 blocks (one wave)
    pu_gemm_kernel<<<gridA, 512, smemA>>>(q, et);

    dim3 gridB(Ss / QG, Bb);                 // 128 x 2 = 256 blocks
    scatter_kernel<<<gridB, 256>>>(out, xw, mxp);
}

// round 6
// speedup vs baseline: 1.2301x; 1.1100x over previous
#include <cuda_runtime.h>
#include <cstddef>

// Problem constants
#define Bb 2
#define Ss 512
#define Hh 8
#define Dd 64
#define Ee 512          // H*D
#define QT 64           // q rows per block
#define NRU 256         // relative index r in [0,256)
#define EP  66          // sE pitch ([r][d] layout, conflict-free LDS.64)
#define PUP 257         // sPu pitch (odd -> conflict-free scalar access)

// ---- Fully fused kernel ----
// Grid = (8 qtiles, 16 b*h) = 128 blocks (one balanced wave), 512 threads.
// Phase 1: Pu[qi][r] = sum_d Q[b,q0+qi,h,d] * E[r, h*64+d]   (f32x2, d-parity packing)
// Phase 2: out[b,h,q0+qi,k] = Pu[qi][ mx + x[b,k] - x[b,q0+qi] ]
__global__ __launch_bounds__(512)
void relpos_fused_kernel(const float* __restrict__ qin,
                         const float* __restrict__ et,
                         const int*   __restrict__ xw,
                         const int*   __restrict__ mxp,
                         float*       __restrict__ out)
{
    extern __shared__ float sm[];
    float* sE  = sm;                  // [NRU][EP]  E slice, row-major [r][d]  (67,584 B)
    float* sQ  = sm + NRU * EP;       // [QT][Dd]   row-major [q][d]           (16,384 B)
    float* sPu = sm;                  // [QT][PUP]  overlaid on sE after GEMM  (65,792 B)
    __shared__ int sX[Ss];
    __shared__ int sIs64;

    const int tid = threadIdx.x;
    const int q0  = blockIdx.x * QT;
    const int h   = blockIdx.y & 7;
    const int b   = blockIdx.y >> 3;

    // dtype detection: int64 x -> odd 32-bit words of the first 4 KB are all zero.
    if (tid == 0) sIs64 = 1;
    // E slice: global coalesced over d, smem [r][d].
    for (int i = tid; i < NRU * Dd; i += 512) {
        const int r = i >> 6, d = i & 63;
        sE[r * EP + d] = et[r * Ee + h * Dd + d];
    }
    // Q tile: coalesced over d.
    for (int i = tid; i < QT * Dd; i += 512) {
        const int qi = i >> 6, d = i & 63;
        sQ[i] = qin[(((size_t)b * Ss + q0 + qi) * Hh + h) * Dd + d];
    }
    if (xw[2 * tid + 1] != 0) atomicAnd(&sIs64, 0);
    __syncthreads();

    // ---- Phase 1: GEMM. Warp w: q rows {4w..4w+3}; lane l: r in {l+32j}, j<8 ----
    const int l = tid & 31;
    const int w = tid >> 5;

    unsigned long long acc[4][8];
    #pragma unroll
    for (int i = 0; i < 4; ++i)
        #pragma unroll
        for (int j = 0; j < 8; ++j) acc[i][j] = 0ULL;

    #pragma unroll 2
    for (int d = 0; d < Dd; d += 2) {
        unsigned long long e2[8], q2[4];
        #pragma unroll
        for (int j = 0; j < 8; ++j)   // LDS.64 (E[r][d], E[r][d+1])
            e2[j] = *(const unsigned long long*)&sE[(l + 32 * j) * EP + d];
        #pragma unroll
        for (int i = 0; i < 4; ++i)   // LDS.64 (q[d], q[d+1]); warp-broadcast
            q2[i] = *(const unsigned long long*)&sQ[(4 * w + i) * Dd + d];
        #pragma unroll
        for (int i = 0; i < 4; ++i)
            #pragma unroll
            for (int j = 0; j < 8; ++j)
                asm("fma.rn.f32x2 %0, %1, %2, %3;"
                    : "=l"(acc[i][j]) : "l"(q2[i]), "l"(e2[j]), "l"(acc[i][j]));
    }
    __syncthreads();   // all warps done reading sE/sQ

    // ---- Stage Pu into smem (overlaid on sE). Bank: (257*q + l) % 32 -> conflict-free ----
    #pragma unroll
    for (int i = 0; i < 4; ++i)
        #pragma unroll
        for (int j = 0; j < 8; ++j) {
            float lo, hi;
            asm("mov.b64 {%0, %1}, %2;" : "=f"(lo), "=f"(hi) : "l"(acc[i][j]));
            sPu[(4 * w + i) * PUP + l + 32 * j] = lo + hi;
        }

    // x row for this batch, normalized to int32 (sIs64 valid since first sync).
    if (sIs64) sX[tid] = xw[2 * (b * Ss + tid)];
    else       sX[tid] = xw[b * Ss + tid];
    __syncthreads();

    // ---- Phase 2: epilogue scatter. Thread t: q row = t>>3, k quads strided by 8 ----
    const int mx  = mxp ? mxp[0] : 128;      // LE low word valid for int32/int64
    const int qi  = tid >> 3;                // 0..63
    const int kc  = tid & 7;                 // k-quad column
    const int off = mx - sX[q0 + qi];
    const float* p = &sPu[qi * PUP];
    float* orow = out + (((size_t)(b * Hh + h) * Ss + q0 + qi)) * Ss;

    #pragma unroll
    for (int it = 0; it < 16; ++it) {
        const int k0 = (kc + 8 * it) * 4;
        float4 v;
        v.x = p[off + sX[k0]];
        v.y = p[off + sX[k0 + 1]];
        v.z = p[off + sX[k0 + 2]];
        v.w = p[off + sX[k0 + 3]];
        *(float4*)&orow[k0] = v;             // STG.128, 64B-contiguous per 4-lane group
    }
}

extern "C" void kernel_launch(void* const* d_in, const int* in_sizes, int n_in,
                              void* d_out, int out_size) {
    const float* q   = (const float*)d_in[0];
    const float* et  = (const float*)d_in[1];
    const int*   xw  = (const int*)d_in[2];
    const int*   mxp = (n_in > 3) ? (const int*)d_in[3] : nullptr;
    float*       out = (float*)d_out;
    (void)in_sizes; (void)out_size;

    const int smem = (NRU * EP + QT * Dd) * sizeof(float);  // 83,968 B
    cudaFuncSetAttribute(relpos_fused_kernel,
                         cudaFuncAttributeMaxDynamicSharedMemorySize, smem);

    dim3 grid(Ss / QT, Hh * Bb);             // 8 x 16 = 128 blocks (one wave)
    relpos_fused_kernel<<<grid, 512, smem>>>(q, et, xw, mxp, out);
}